// round 1
// baseline (speedup 1.0000x reference)
#include <cuda_runtime.h>
#include <math.h>

#define B_   4
#define T_   1024
#define E_   1024
#define H_   16
#define DK_  64
#define M_   (B_ * T_)        // 4096 rows
static __device__ __constant__ float kSCALE = 0.125f;   // 64^-0.5
static __device__ __constant__ float kWEPS  = 1e-5f;

// Scratch (allocation-free rule: __device__ globals)
__device__ float g_Q[M_ * E_];
__device__ float g_K[M_ * E_];
__device__ float g_V[M_ * E_];
__device__ float g_O[M_ * E_];

// ---------------------------------------------------------------------------
// SGEMM:  C[M,N] = A[M,K] @ W[N,K]^T + bias[N]     (all row-major fp32)
// 128x128 block tile, BK=16, 8x8 per-thread tile, 256 threads.
// ---------------------------------------------------------------------------
#define BM 128
#define BN 128
#define BK 16
#define TM 8
#define TN 8

__global__ void __launch_bounds__(256)
gemm_nt_bias(const float* __restrict__ A,
             const float* __restrict__ W,
             const float* __restrict__ bias,
             float* __restrict__ C,
             int Mdim, int Ndim, int Kdim)
{
    __shared__ float As[BK][BM];
    __shared__ float Bs[BK][BN];

    const int tid  = threadIdx.x;
    const int cCol = blockIdx.x;   // N tile
    const int cRow = blockIdx.y;   // M tile

    const float* Ab = A + (size_t)cRow * BM * Kdim;
    const float* Wb = W + (size_t)cCol * BN * Kdim;

    const int loadRow = tid >> 2;        // 0..63
    const int loadCol = (tid & 3) << 2;  // 0,4,8,12
    const int tRow = tid >> 4;           // 0..15
    const int tCol = tid & 15;           // 0..15

    float acc[TM][TN] = {};
    float regM[TM], regN[TN];

    for (int k0 = 0; k0 < Kdim; k0 += BK) {
        // load A tile (128x16) transposed into As[k][m]
        #pragma unroll
        for (int r = 0; r < BM; r += 64) {
            float4 v = *(const float4*)(Ab + (size_t)(loadRow + r) * Kdim + k0 + loadCol);
            As[loadCol + 0][loadRow + r] = v.x;
            As[loadCol + 1][loadRow + r] = v.y;
            As[loadCol + 2][loadRow + r] = v.z;
            As[loadCol + 3][loadRow + r] = v.w;
        }
        // load W tile (128x16) transposed into Bs[k][n]
        #pragma unroll
        for (int r = 0; r < BN; r += 64) {
            float4 v = *(const float4*)(Wb + (size_t)(loadRow + r) * Kdim + k0 + loadCol);
            Bs[loadCol + 0][loadRow + r] = v.x;
            Bs[loadCol + 1][loadRow + r] = v.y;
            Bs[loadCol + 2][loadRow + r] = v.z;
            Bs[loadCol + 3][loadRow + r] = v.w;
        }
        __syncthreads();

        #pragma unroll
        for (int kk = 0; kk < BK; kk++) {
            #pragma unroll
            for (int i = 0; i < TM; i++) regM[i] = As[kk][tRow * TM + i];
            #pragma unroll
            for (int j = 0; j < TN; j++) regN[j] = Bs[kk][tCol * TN + j];
            #pragma unroll
            for (int i = 0; i < TM; i++)
                #pragma unroll
                for (int j = 0; j < TN; j++)
                    acc[i][j] += regM[i] * regN[j];
        }
        __syncthreads();
    }

    // epilogue with bias, float4 stores
    #pragma unroll
    for (int i = 0; i < TM; i++) {
        const int gm = cRow * BM + tRow * TM + i;
        float* crow = C + (size_t)gm * Ndim + cCol * BN + tCol * TN;
        const float* brow = bias + cCol * BN + tCol * TN;
        #pragma unroll
        for (int j = 0; j < TN; j += 4) {
            float4 o;
            o.x = acc[i][j + 0] + brow[j + 0];
            o.y = acc[i][j + 1] + brow[j + 1];
            o.z = acc[i][j + 2] + brow[j + 2];
            o.w = acc[i][j + 3] + brow[j + 3];
            *(float4*)(crow + j) = o;
        }
    }
}

// ---------------------------------------------------------------------------
// Fused weighted attention, flash-style online softmax.
// grid = (T/128, H, B), 128 threads; 1 query row per thread.
// K/V tiles (64 keys x 64 dims) staged in smem; w mask folded into scale.
// ---------------------------------------------------------------------------
__global__ void __launch_bounds__(128)
attn_kernel(const float* __restrict__ Qp,
            const float* __restrict__ Kp,
            const float* __restrict__ Vp,
            const float* __restrict__ w,
            float* __restrict__ Op)
{
    const int b   = blockIdx.z;
    const int h   = blockIdx.y;
    const int q0  = blockIdx.x * 128;
    const int tid = threadIdx.x;

    __shared__ float Ks[64 * 64];
    __shared__ float Vs[64 * 64];
    __shared__ float ws2[64];       // w*w*scale, or -1 sentinel if masked

    // Q row into registers
    float q[DK_];
    const float* qrow = Qp + ((size_t)(b * T_) + q0 + tid) * E_ + h * DK_;
    #pragma unroll
    for (int d = 0; d < DK_; d += 4)
        *(float4*)&q[d] = *(const float4*)&qrow[d];

    float m = -INFINITY, l = 0.f;
    float acc[DK_] = {};

    for (int k0 = 0; k0 < T_; k0 += 64) {
        const float* Kb = Kp + ((size_t)(b * T_) + k0) * E_ + h * DK_;
        const float* Vb = Vp + ((size_t)(b * T_) + k0) * E_ + h * DK_;

        __syncthreads();   // protect previous-iteration smem reads
        for (int i = tid; i < 64 * 16; i += 128) {
            const int r = i >> 4;
            const int c = (i & 15) << 2;
            *(float4*)&Ks[r * 64 + c] = *(const float4*)&Kb[(size_t)r * E_ + c];
            *(float4*)&Vs[r * 64 + c] = *(const float4*)&Vb[(size_t)r * E_ + c];
        }
        if (tid < 64) {
            const float wv = w[b * T_ + k0 + tid];
            ws2[tid] = (wv < kWEPS) ? -1.f : wv * wv * kSCALE;
        }
        __syncthreads();

        #pragma unroll 2
        for (int j = 0; j < 64; j++) {
            const float wj = ws2[j];
            if (wj < 0.f) continue;           // masked key: exp(-inf)=0, skip

            float s = 0.f;
            #pragma unroll
            for (int d = 0; d < DK_; d += 4) {
                const float4 kv = *(const float4*)&Ks[j * 64 + d];
                s += q[d] * kv.x + q[d + 1] * kv.y + q[d + 2] * kv.z + q[d + 3] * kv.w;
            }
            s *= wj;

            if (s > m) {                       // lazy rescale
                const float corr = __expf(m - s);   // m=-inf first hit -> 0
                m = s;
                l *= corr;
                #pragma unroll
                for (int d = 0; d < DK_; d++) acc[d] *= corr;
            }
            const float p = __expf(s - m);
            l += p;
            #pragma unroll
            for (int d = 0; d < DK_; d += 4) {
                const float4 vv = *(const float4*)&Vs[j * 64 + d];
                acc[d + 0] += p * vv.x;
                acc[d + 1] += p * vv.y;
                acc[d + 2] += p * vv.z;
                acc[d + 3] += p * vv.w;
            }
        }
    }

    const float inv = 1.f / l;
    float* orow = Op + ((size_t)(b * T_) + q0 + tid) * E_ + h * DK_;
    #pragma unroll
    for (int d = 0; d < DK_; d += 4) {
        float4 o;
        o.x = acc[d + 0] * inv;
        o.y = acc[d + 1] * inv;
        o.z = acc[d + 2] * inv;
        o.w = acc[d + 3] * inv;
        *(float4*)&orow[d] = o;
    }
}

// ---------------------------------------------------------------------------
extern "C" void kernel_launch(void* const* d_in, const int* in_sizes, int n_in,
                              void* d_out, int out_size)
{
    const float* q  = (const float*)d_in[0];
    const float* k  = (const float*)d_in[1];
    const float* v  = (const float*)d_in[2];
    const float* w  = (const float*)d_in[3];
    const float* Wq = (const float*)d_in[4];
    const float* bq = (const float*)d_in[5];
    const float* Wk = (const float*)d_in[6];
    const float* bk = (const float*)d_in[7];
    const float* Wv = (const float*)d_in[8];
    const float* bv = (const float*)d_in[9];
    const float* Wo = (const float*)d_in[10];
    const float* bo = (const float*)d_in[11];
    float* out = (float*)d_out;

    float *Qp, *Kp, *Vp, *Op;
    cudaGetSymbolAddress((void**)&Qp, g_Q);
    cudaGetSymbolAddress((void**)&Kp, g_K);
    cudaGetSymbolAddress((void**)&Vp, g_V);
    cudaGetSymbolAddress((void**)&Op, g_O);

    const dim3 gGrid(E_ / BN, M_ / BM);   // (8, 32)
    gemm_nt_bias<<<gGrid, 256>>>(q, Wq, bq, Qp, M_, E_, E_);
    gemm_nt_bias<<<gGrid, 256>>>(k, Wk, bk, Kp, M_, E_, E_);
    gemm_nt_bias<<<gGrid, 256>>>(v, Wv, bv, Vp, M_, E_, E_);

    const dim3 aGrid(T_ / 128, H_, B_);   // (8, 16, 4)
    attn_kernel<<<aGrid, 128>>>(Qp, Kp, Vp, w, Op);

    gemm_nt_bias<<<gGrid, 256>>>(Op, Wo, bo, out, M_, E_, E_);
}

// round 4
// speedup vs baseline: 2.6785x; 2.6785x over previous
#include <cuda_runtime.h>
#include <math.h>
#include <stdint.h>

#define B_   4
#define T_   1024
#define E_   1024
#define H_   16
#define DK_  64
#define M_   (B_ * T_)        // 4096 rows
static __device__ __constant__ float kSCALE = 0.125f;   // 64^-0.5
static __device__ __constant__ float kWEPS  = 1e-5f;

// Scratch (allocation-free rule: __device__ globals)
__device__ float g_Q[M_ * E_];
__device__ float g_K[M_ * E_];
__device__ float g_V[M_ * E_];
__device__ float g_O[M_ * E_];

// ---------------------------------------------------------------------------
// helpers
// ---------------------------------------------------------------------------
__device__ __forceinline__ uint32_t smem_u32(const void* p) {
    uint32_t a;
    asm("{ .reg .u64 t; cvta.to.shared.u64 t, %1; cvt.u32.u64 %0, t; }"
        : "=r"(a) : "l"(p));
    return a;
}
__device__ __forceinline__ void cp_async16(uint32_t sdst, const void* gsrc) {
    asm volatile("cp.async.cg.shared.global [%0], [%1], 16;"
                 :: "r"(sdst), "l"(gsrc) : "memory");
}
#define CP_COMMIT() asm volatile("cp.async.commit_group;" ::: "memory")
#define CP_WAIT(n)  asm volatile("cp.async.wait_group %0;" :: "n"(n) : "memory")

__device__ __forceinline__ uint32_t f2tf32(float f) {
    uint32_t r;
    asm("cvt.rna.tf32.f32 %0, %1;" : "=r"(r) : "f"(f));
    return r;
}

__device__ __forceinline__ void mma_tf32(float* c, const uint32_t* a, const uint32_t* b) {
    asm volatile(
        "mma.sync.aligned.m16n8k8.row.col.f32.tf32.tf32.f32 "
        "{%0,%1,%2,%3}, {%4,%5,%6,%7}, {%8,%9}, {%0,%1,%2,%3};"
        : "+f"(c[0]), "+f"(c[1]), "+f"(c[2]), "+f"(c[3])
        : "r"(a[0]), "r"(a[1]), "r"(a[2]), "r"(a[3]), "r"(b[0]), "r"(b[1]));
}

// ---------------------------------------------------------------------------
// tf32 mma.sync GEMM:  C[4096,1024] = A[4096,1024] @ W[1024,1024]^T + bias
// 128x128 CTA tile, BK=32, 256 threads (8 warps 4x2), warp tile 32x64.
// Double-buffered cp.async; smem stride 36 floats (conflict-free frag LDS).
// ---------------------------------------------------------------------------
#define GBM 128
#define GBN 128
#define GBK 32
#define SSTRIDE 36
#define STAGE_FLOATS (GBM * SSTRIDE)                 // per-tile (A or B)
#define GEMM_SMEM    (2 * 2 * STAGE_FLOATS * 4)      // 73728 bytes

__global__ void __launch_bounds__(256)
gemm_tc(const float* __restrict__ A,
        const float* __restrict__ W,
        const float* __restrict__ bias,
        float* __restrict__ C)
{
    extern __shared__ __align__(16) float smem[];
    float* As = smem;                          // [2][128][36]
    float* Bs = smem + 2 * STAGE_FLOATS;       // [2][128][36]
    const uint32_t sAs = smem_u32(As);
    const uint32_t sBs = smem_u32(Bs);

    const int tid  = threadIdx.x;
    const int wid  = tid >> 5;
    const int lane = tid & 31;
    const int g    = lane >> 2;     // 0..7
    const int t    = lane & 3;      // 0..3
    const int wm   = (wid >> 1) * 32;
    const int wn   = (wid & 1) * 64;
    const int m0   = blockIdx.y * GBM;
    const int n0   = blockIdx.x * GBN;

    // copy indexing: 1024 float4-chunks per tile, 4 per thread
    const int crow = tid >> 1;              // 0..127  (2 chunks per row handled below)
    // per tile: 128 rows x 8 chunks; thread handles chunk id = tid + i*256
    float acc[2][8][4] = {};

    // ---- pipeline ----
    const int KTILES = E_ / GBK;   // 32
    (void)crow;

    // prologue: stage 0
    {
        #pragma unroll
        for (int i = 0; i < 4; i++) {
            const int id = tid + i * 256;
            const int r  = id >> 3;
            const int c4 = (id & 7) * 4;
            cp_async16(sAs + (r * SSTRIDE + c4) * 4, A + (size_t)(m0 + r) * E_ + c4);
            cp_async16(sBs + (r * SSTRIDE + c4) * 4, W + (size_t)(n0 + r) * E_ + c4);
        }
        CP_COMMIT();
    }

    for (int kt = 0; kt < KTILES; kt++) {
        const int s = kt & 1;

        if (kt + 1 < KTILES) {
            const int ns = 1 - s;
            const int kc = (kt + 1) * GBK;
            #pragma unroll
            for (int i = 0; i < 4; i++) {
                const int id = tid + i * 256;
                const int r  = id >> 3;
                const int c4 = (id & 7) * 4;
                cp_async16(sAs + (ns * STAGE_FLOATS + r * SSTRIDE + c4) * 4,
                           A + (size_t)(m0 + r) * E_ + kc + c4);
                cp_async16(sBs + (ns * STAGE_FLOATS + r * SSTRIDE + c4) * 4,
                           W + (size_t)(n0 + r) * E_ + kc + c4);
            }
            CP_COMMIT();
            CP_WAIT(1);
        } else {
            CP_WAIT(0);
        }
        __syncthreads();

        const float* Asl = As + s * STAGE_FLOATS;
        const float* Bsl = Bs + s * STAGE_FLOATS;

        #pragma unroll
        for (int kk = 0; kk < 4; kk++) {
            const int kb = kk * 8;
            // B fragments: 8 n-tiles x 2 regs
            uint32_t bf[8][2];
            #pragma unroll
            for (int ni = 0; ni < 8; ni++) {
                const int n = wn + ni * 8 + g;
                bf[ni][0] = f2tf32(Bsl[n * SSTRIDE + kb + t]);
                bf[ni][1] = f2tf32(Bsl[n * SSTRIDE + kb + t + 4]);
            }
            #pragma unroll
            for (int mi = 0; mi < 2; mi++) {
                const int r = wm + mi * 16;
                uint32_t af[4];
                af[0] = f2tf32(Asl[(r + g)     * SSTRIDE + kb + t]);
                af[1] = f2tf32(Asl[(r + g + 8) * SSTRIDE + kb + t]);
                af[2] = f2tf32(Asl[(r + g)     * SSTRIDE + kb + t + 4]);
                af[3] = f2tf32(Asl[(r + g + 8) * SSTRIDE + kb + t + 4]);
                #pragma unroll
                for (int ni = 0; ni < 8; ni++)
                    mma_tf32(acc[mi][ni], af, bf[ni]);
            }
        }
        __syncthreads();
    }

    // ---- epilogue: direct stores with bias ----
    #pragma unroll
    for (int ni = 0; ni < 8; ni++) {
        const int col = n0 + wn + ni * 8 + 2 * t;
        const float2 bv = *(const float2*)(bias + col);
        #pragma unroll
        for (int mi = 0; mi < 2; mi++) {
            const int r0 = m0 + wm + mi * 16 + g;
            float2 o0, o1;
            o0.x = acc[mi][ni][0] + bv.x;
            o0.y = acc[mi][ni][1] + bv.y;
            o1.x = acc[mi][ni][2] + bv.x;
            o1.y = acc[mi][ni][3] + bv.y;
            *(float2*)(C + (size_t)r0 * E_ + col)       = o0;
            *(float2*)(C + (size_t)(r0 + 8) * E_ + col) = o1;
        }
    }
}

// ---------------------------------------------------------------------------
// Fused weighted attention, flash-style online softmax (unchanged from R0).
// ---------------------------------------------------------------------------
__global__ void __launch_bounds__(128)
attn_kernel(const float* __restrict__ Qp,
            const float* __restrict__ Kp,
            const float* __restrict__ Vp,
            const float* __restrict__ w,
            float* __restrict__ Op)
{
    const int b   = blockIdx.z;
    const int h   = blockIdx.y;
    const int q0  = blockIdx.x * 128;
    const int tid = threadIdx.x;

    __shared__ float Ks[64 * 64];
    __shared__ float Vs[64 * 64];
    __shared__ float ws2[64];

    float q[DK_];
    const float* qrow = Qp + ((size_t)(b * T_) + q0 + tid) * E_ + h * DK_;
    #pragma unroll
    for (int d = 0; d < DK_; d += 4)
        *(float4*)&q[d] = *(const float4*)&qrow[d];

    float m = -INFINITY, l = 0.f;
    float acc[DK_] = {};

    for (int k0 = 0; k0 < T_; k0 += 64) {
        const float* Kb = Kp + ((size_t)(b * T_) + k0) * E_ + h * DK_;
        const float* Vb = Vp + ((size_t)(b * T_) + k0) * E_ + h * DK_;

        __syncthreads();
        for (int i = tid; i < 64 * 16; i += 128) {
            const int r = i >> 4;
            const int c = (i & 15) << 2;
            *(float4*)&Ks[r * 64 + c] = *(const float4*)&Kb[(size_t)r * E_ + c];
            *(float4*)&Vs[r * 64 + c] = *(const float4*)&Vb[(size_t)r * E_ + c];
        }
        if (tid < 64) {
            const float wv = w[b * T_ + k0 + tid];
            ws2[tid] = (wv < kWEPS) ? -1.f : wv * wv * kSCALE;
        }
        __syncthreads();

        #pragma unroll 2
        for (int j = 0; j < 64; j++) {
            const float wj = ws2[j];
            if (wj < 0.f) continue;

            float s = 0.f;
            #pragma unroll
            for (int d = 0; d < DK_; d += 4) {
                const float4 kv = *(const float4*)&Ks[j * 64 + d];
                s += q[d] * kv.x + q[d + 1] * kv.y + q[d + 2] * kv.z + q[d + 3] * kv.w;
            }
            s *= wj;

            if (s > m) {
                const float corr = __expf(m - s);
                m = s;
                l *= corr;
                #pragma unroll
                for (int d = 0; d < DK_; d++) acc[d] *= corr;
            }
            const float p = __expf(s - m);
            l += p;
            #pragma unroll
            for (int d = 0; d < DK_; d += 4) {
                const float4 vv = *(const float4*)&Vs[j * 64 + d];
                acc[d + 0] += p * vv.x;
                acc[d + 1] += p * vv.y;
                acc[d + 2] += p * vv.z;
                acc[d + 3] += p * vv.w;
            }
        }
    }

    const float inv = 1.f / l;
    float* orow = Op + ((size_t)(b * T_) + q0 + tid) * E_ + h * DK_;
    #pragma unroll
    for (int d = 0; d < DK_; d += 4) {
        float4 o;
        o.x = acc[d + 0] * inv;
        o.y = acc[d + 1] * inv;
        o.z = acc[d + 2] * inv;
        o.w = acc[d + 3] * inv;
        *(float4*)&orow[d] = o;
    }
}

// ---------------------------------------------------------------------------
extern "C" void kernel_launch(void* const* d_in, const int* in_sizes, int n_in,
                              void* d_out, int out_size)
{
    const float* q  = (const float*)d_in[0];
    const float* k  = (const float*)d_in[1];
    const float* v  = (const float*)d_in[2];
    const float* w  = (const float*)d_in[3];
    const float* Wq = (const float*)d_in[4];
    const float* bq = (const float*)d_in[5];
    const float* Wk = (const float*)d_in[6];
    const float* bk = (const float*)d_in[7];
    const float* Wv = (const float*)d_in[8];
    const float* bv = (const float*)d_in[9];
    const float* Wo = (const float*)d_in[10];
    const float* bo = (const float*)d_in[11];
    float* out = (float*)d_out;

    float *Qp, *Kp, *Vp, *Op;
    cudaGetSymbolAddress((void**)&Qp, g_Q);
    cudaGetSymbolAddress((void**)&Kp, g_K);
    cudaGetSymbolAddress((void**)&Vp, g_V);
    cudaGetSymbolAddress((void**)&Op, g_O);

    cudaFuncSetAttribute(gemm_tc, cudaFuncAttributeMaxDynamicSharedMemorySize, GEMM_SMEM);

    const dim3 gGrid(E_ / GBN, M_ / GBM);   // (8, 32)
    gemm_tc<<<gGrid, 256, GEMM_SMEM>>>(q, Wq, bq, Qp);
    gemm_tc<<<gGrid, 256, GEMM_SMEM>>>(k, Wk, bk, Kp);
    gemm_tc<<<gGrid, 256, GEMM_SMEM>>>(v, Wv, bv, Vp);

    const dim3 aGrid(T_ / 128, H_, B_);   // (8, 16, 4)
    attn_kernel<<<aGrid, 128>>>(Qp, Kp, Vp, w, Op);

    gemm_tc<<<gGrid, 256, GEMM_SMEM>>>(Op, Wo, bo, out);
}

// round 5
// speedup vs baseline: 6.2962x; 2.3506x over previous
#include <cuda_runtime.h>
#include <math.h>
#include <stdint.h>

#define B_   4
#define T_   1024
#define E_   1024
#define H_   16
#define DK_  64
#define M_   (B_ * T_)        // 4096 rows

// Scratch (allocation-free rule: __device__ globals)
__device__ float g_Q[M_ * E_];
__device__ float g_K[M_ * E_];
__device__ float g_V[M_ * E_];
__device__ float g_O[M_ * E_];

// ---------------------------------------------------------------------------
// helpers
// ---------------------------------------------------------------------------
__device__ __forceinline__ uint32_t smem_u32(const void* p) {
    uint32_t a;
    asm("{ .reg .u64 t; cvta.to.shared.u64 t, %1; cvt.u32.u64 %0, t; }"
        : "=r"(a) : "l"(p));
    return a;
}
__device__ __forceinline__ void cp_async16(uint32_t sdst, const void* gsrc) {
    asm volatile("cp.async.cg.shared.global [%0], [%1], 16;"
                 :: "r"(sdst), "l"(gsrc) : "memory");
}
#define CP_COMMIT() asm volatile("cp.async.commit_group;" ::: "memory")
#define CP_WAIT(n)  asm volatile("cp.async.wait_group %0;" :: "n"(n) : "memory")

__device__ __forceinline__ uint32_t f2tf32(float f) {
    uint32_t r;
    asm("cvt.rna.tf32.f32 %0, %1;" : "=r"(r) : "f"(f));
    return r;
}
__device__ __forceinline__ float ex2(float x) {
    float r; asm("ex2.approx.f32 %0, %1;" : "=f"(r) : "f"(x)); return r;
}
__device__ __forceinline__ void mma_tf32(float* c, const uint32_t* a, const uint32_t* b) {
    asm volatile(
        "mma.sync.aligned.m16n8k8.row.col.f32.tf32.tf32.f32 "
        "{%0,%1,%2,%3}, {%4,%5,%6,%7}, {%8,%9}, {%0,%1,%2,%3};"
        : "+f"(c[0]), "+f"(c[1]), "+f"(c[2]), "+f"(c[3])
        : "r"(a[0]), "r"(a[1]), "r"(a[2]), "r"(a[3]), "r"(b[0]), "r"(b[1]));
}

// ---------------------------------------------------------------------------
// tf32 mma.sync GEMM core:  C[4096,1024] = A[4096,1024] @ W[1024,1024]^T + bias
// 128x128 CTA tile, BK=32, 256 threads (8 warps 4x2), warp tile 32x64.
// ROUND=1: store outputs pre-rounded to tf32 (consumed by tensor-core attn).
// ---------------------------------------------------------------------------
#define GBM 128
#define GBN 128
#define GBK 32
#define SSTRIDE 36
#define STAGE_FLOATS (GBM * SSTRIDE)
#define GEMM_SMEM    (2 * 2 * STAGE_FLOATS * 4)      // 73728 bytes

template<int ROUND>
__device__ __forceinline__ void gemm_core(const float* __restrict__ A,
                                          const float* __restrict__ W,
                                          const float* __restrict__ bias,
                                          float* __restrict__ C)
{
    extern __shared__ __align__(16) float smem[];
    float* As = smem;                          // [2][128][36]
    float* Bs = smem + 2 * STAGE_FLOATS;       // [2][128][36]
    const uint32_t sAs = smem_u32(As);
    const uint32_t sBs = smem_u32(Bs);

    const int tid  = threadIdx.x;
    const int wid  = tid >> 5;
    const int lane = tid & 31;
    const int g    = lane >> 2;
    const int t    = lane & 3;
    const int wm   = (wid >> 1) * 32;
    const int wn   = (wid & 1) * 64;
    const int m0   = blockIdx.y * GBM;
    const int n0   = blockIdx.x * GBN;

    float acc[2][8][4] = {};
    const int KTILES = E_ / GBK;

    {
        #pragma unroll
        for (int i = 0; i < 4; i++) {
            const int id = tid + i * 256;
            const int r  = id >> 3;
            const int c4 = (id & 7) * 4;
            cp_async16(sAs + (r * SSTRIDE + c4) * 4, A + (size_t)(m0 + r) * E_ + c4);
            cp_async16(sBs + (r * SSTRIDE + c4) * 4, W + (size_t)(n0 + r) * E_ + c4);
        }
        CP_COMMIT();
    }

    for (int kt = 0; kt < KTILES; kt++) {
        const int s = kt & 1;

        if (kt + 1 < KTILES) {
            const int ns = 1 - s;
            const int kc = (kt + 1) * GBK;
            #pragma unroll
            for (int i = 0; i < 4; i++) {
                const int id = tid + i * 256;
                const int r  = id >> 3;
                const int c4 = (id & 7) * 4;
                cp_async16(sAs + (ns * STAGE_FLOATS + r * SSTRIDE + c4) * 4,
                           A + (size_t)(m0 + r) * E_ + kc + c4);
                cp_async16(sBs + (ns * STAGE_FLOATS + r * SSTRIDE + c4) * 4,
                           W + (size_t)(n0 + r) * E_ + kc + c4);
            }
            CP_COMMIT();
            CP_WAIT(1);
        } else {
            CP_WAIT(0);
        }
        __syncthreads();

        const float* Asl = As + s * STAGE_FLOATS;
        const float* Bsl = Bs + s * STAGE_FLOATS;

        #pragma unroll
        for (int kk = 0; kk < 4; kk++) {
            const int kb = kk * 8;
            uint32_t bf[8][2];
            #pragma unroll
            for (int ni = 0; ni < 8; ni++) {
                const int n = wn + ni * 8 + g;
                bf[ni][0] = f2tf32(Bsl[n * SSTRIDE + kb + t]);
                bf[ni][1] = f2tf32(Bsl[n * SSTRIDE + kb + t + 4]);
            }
            #pragma unroll
            for (int mi = 0; mi < 2; mi++) {
                const int r = wm + mi * 16;
                uint32_t af[4];
                af[0] = f2tf32(Asl[(r + g)     * SSTRIDE + kb + t]);
                af[1] = f2tf32(Asl[(r + g + 8) * SSTRIDE + kb + t]);
                af[2] = f2tf32(Asl[(r + g)     * SSTRIDE + kb + t + 4]);
                af[3] = f2tf32(Asl[(r + g + 8) * SSTRIDE + kb + t + 4]);
                #pragma unroll
                for (int ni = 0; ni < 8; ni++)
                    mma_tf32(acc[mi][ni], af, bf[ni]);
            }
        }
        __syncthreads();
    }

    #pragma unroll
    for (int ni = 0; ni < 8; ni++) {
        const int col = n0 + wn + ni * 8 + 2 * t;
        const float2 bv = *(const float2*)(bias + col);
        #pragma unroll
        for (int mi = 0; mi < 2; mi++) {
            const int r0 = m0 + wm + mi * 16 + g;
            float2 o0, o1;
            o0.x = acc[mi][ni][0] + bv.x;
            o0.y = acc[mi][ni][1] + bv.y;
            o1.x = acc[mi][ni][2] + bv.x;
            o1.y = acc[mi][ni][3] + bv.y;
            if (ROUND) {
                o0.x = __uint_as_float(f2tf32(o0.x));
                o0.y = __uint_as_float(f2tf32(o0.y));
                o1.x = __uint_as_float(f2tf32(o1.x));
                o1.y = __uint_as_float(f2tf32(o1.y));
            }
            *(float2*)(C + (size_t)r0 * E_ + col)       = o0;
            *(float2*)(C + (size_t)(r0 + 8) * E_ + col) = o1;
        }
    }
}

// Merged Q/K/V projections: gridDim.z selects which; outputs tf32-rounded.
__global__ void __launch_bounds__(256)
gemm_qkv(const float* __restrict__ q,  const float* __restrict__ k,  const float* __restrict__ v,
         const float* __restrict__ Wq, const float* __restrict__ Wk, const float* __restrict__ Wv,
         const float* __restrict__ bq, const float* __restrict__ bk, const float* __restrict__ bv,
         float* __restrict__ Cq, float* __restrict__ Ck, float* __restrict__ Cv)
{
    const int z = blockIdx.z;
    if (z == 0)      gemm_core<1>(q, Wq, bq, Cq);
    else if (z == 1) gemm_core<1>(k, Wk, bk, Ck);
    else             gemm_core<1>(v, Wv, bv, Cv);
}

__global__ void __launch_bounds__(256)
gemm_o(const float* __restrict__ A, const float* __restrict__ W,
       const float* __restrict__ bias, float* __restrict__ C)
{
    gemm_core<0>(A, W, bias, C);
}

// ---------------------------------------------------------------------------
// Tensor-core flash attention.
// grid (T/128, H, B) = (8,16,4), 256 threads = 8 warps x 16 query rows.
// Key tiles of 64, double-buffered cp.async. tf32 mma for QK^T and PV.
// Q/K/V are pre-rounded tf32 in memory -> no cvt in hot loop.
// ---------------------------------------------------------------------------
#define AST 68                                  // smem stride (floats)
#define KVSTG (64 * AST)                        // 4352 floats per tile
#define KS_OFF(s) ((s) * 2 * KVSTG)
#define VS_OFF(s) ((s) * 2 * KVSTG + KVSTG)
#define WS_OFF(s) (4 * KVSTG + (s) * 128)
#define QS_OFF    (4 * KVSTG + 256)
#define ATTN_SMEM ((QS_OFF + 128 * AST) * 4)    // 105472 bytes

__global__ void __launch_bounds__(256, 1)
attn_tc(const float* __restrict__ Qp, const float* __restrict__ Kp,
        const float* __restrict__ Vp, const float* __restrict__ w,
        float* __restrict__ Op)
{
    extern __shared__ __align__(16) float sm[];
    const uint32_t sbase = smem_u32(sm);
    const int b   = blockIdx.z;
    const int h   = blockIdx.y;
    const int q0  = blockIdx.x * 128;
    const int tid = threadIdx.x;
    const int wid = tid >> 5;
    const int lane = tid & 31;
    const int g = lane >> 2;
    const int t = lane & 3;
    const int wq = wid * 16;

    // ---- stage Q tile (group 0) ----
    {
        const float* Qg = Qp + (size_t)(b * T_ + q0) * E_ + h * DK_;
        #pragma unroll
        for (int i = 0; i < 8; i++) {
            const int id = tid + i * 256;       // 0..2047
            const int r  = id >> 4;
            const int c4 = (id & 15) * 4;
            cp_async16(sbase + (QS_OFF + r * AST + c4) * 4, Qg + (size_t)r * E_ + c4);
        }
        CP_COMMIT();
    }
    // ---- stage K/V tile 0 (group 1) ----
    {
        const float* Kg = Kp + (size_t)(b * T_) * E_ + h * DK_;
        const float* Vg = Vp + (size_t)(b * T_) * E_ + h * DK_;
        #pragma unroll
        for (int i = 0; i < 4; i++) {
            const int id = tid + i * 256;       // 0..1023
            const int r  = id >> 4;
            const int c4 = (id & 15) * 4;
            cp_async16(sbase + (KS_OFF(0) + r * AST + c4) * 4, Kg + (size_t)r * E_ + c4);
            cp_async16(sbase + (VS_OFF(0) + r * AST + c4) * 4, Vg + (size_t)r * E_ + c4);
        }
        CP_COMMIT();
    }
    if (tid < 64) {
        const float wv = w[b * T_ + tid];
        sm[WS_OFF(0) + tid * 2 + 0] = wv * wv * 0.125f * 1.44269504f;
        sm[WS_OFF(0) + tid * 2 + 1] = (wv < 1e-5f) ? -INFINITY : 0.0f;
    }

    CP_WAIT(1);          // Q arrived
    __syncthreads();

    // Q fragments (bits already tf32-rounded in memory)
    uint32_t aq[8][4];
    #pragma unroll
    for (int ks = 0; ks < 8; ks++) {
        const int kb = ks * 8;
        aq[ks][0] = __float_as_uint(sm[QS_OFF + (wq + g)     * AST + kb + t]);
        aq[ks][1] = __float_as_uint(sm[QS_OFF + (wq + g + 8) * AST + kb + t]);
        aq[ks][2] = __float_as_uint(sm[QS_OFF + (wq + g)     * AST + kb + t + 4]);
        aq[ks][3] = __float_as_uint(sm[QS_OFF + (wq + g + 8) * AST + kb + t + 4]);
    }

    float acc[8][4] = {};
    float m0 = -INFINITY, m1 = -INFINITY, l0 = 0.f, l1 = 0.f;

    const int NT = T_ / 64;   // 16
    for (int kt = 0; kt < NT; kt++) {
        const int s = kt & 1;

        CP_WAIT(0);
        __syncthreads();      // tile kt resident; stage 1-s free for prefetch

        if (kt + 1 < NT) {
            const int ns = 1 - s;
            const float* Kg = Kp + (size_t)(b * T_ + (kt + 1) * 64) * E_ + h * DK_;
            const float* Vg = Vp + (size_t)(b * T_ + (kt + 1) * 64) * E_ + h * DK_;
            #pragma unroll
            for (int i = 0; i < 4; i++) {
                const int id = tid + i * 256;
                const int r  = id >> 4;
                const int c4 = (id & 15) * 4;
                cp_async16(sbase + (KS_OFF(ns) + r * AST + c4) * 4, Kg + (size_t)r * E_ + c4);
                cp_async16(sbase + (VS_OFF(ns) + r * AST + c4) * 4, Vg + (size_t)r * E_ + c4);
            }
            CP_COMMIT();
            if (tid < 64) {
                const float wv = w[b * T_ + (kt + 1) * 64 + tid];
                sm[WS_OFF(ns) + tid * 2 + 0] = wv * wv * 0.125f * 1.44269504f;
                sm[WS_OFF(ns) + tid * 2 + 1] = (wv < 1e-5f) ? -INFINITY : 0.0f;
            }
        }

        const float* Ksl = sm + KS_OFF(s);
        const float* Vsl = sm + VS_OFF(s);
        const float* wsl = sm + WS_OFF(s);

        // ---- S = Q K^T (16x64 per warp) ----
        float sc[8][4] = {};
        #pragma unroll
        for (int ks = 0; ks < 8; ks++) {
            const int kb = ks * 8;
            #pragma unroll
            for (int nt = 0; nt < 8; nt++) {
                uint32_t bf[2];
                bf[0] = __float_as_uint(Ksl[(nt * 8 + g) * AST + kb + t]);
                bf[1] = __float_as_uint(Ksl[(nt * 8 + g) * AST + kb + t + 4]);
                mma_tf32(sc[nt], aq[ks], bf);
            }
        }

        // ---- scale + mask + row max ----
        float tmax0 = -INFINITY, tmax1 = -INFINITY;
        #pragma unroll
        for (int nt = 0; nt < 8; nt++) {
            const float4 wm4 = *(const float4*)&wsl[(nt * 8 + 2 * t) * 2];
            sc[nt][0] = sc[nt][0] * wm4.x + wm4.y;
            sc[nt][1] = sc[nt][1] * wm4.z + wm4.w;
            sc[nt][2] = sc[nt][2] * wm4.x + wm4.y;
            sc[nt][3] = sc[nt][3] * wm4.z + wm4.w;
            tmax0 = fmaxf(tmax0, fmaxf(sc[nt][0], sc[nt][1]));
            tmax1 = fmaxf(tmax1, fmaxf(sc[nt][2], sc[nt][3]));
        }
        tmax0 = fmaxf(tmax0, __shfl_xor_sync(0xffffffffu, tmax0, 1));
        tmax0 = fmaxf(tmax0, __shfl_xor_sync(0xffffffffu, tmax0, 2));
        tmax1 = fmaxf(tmax1, __shfl_xor_sync(0xffffffffu, tmax1, 1));
        tmax1 = fmaxf(tmax1, __shfl_xor_sync(0xffffffffu, tmax1, 2));

        const float nm0 = fmaxf(m0, tmax0);
        const float nm1 = fmaxf(m1, tmax1);
        const float sm0 = fmaxf(nm0, -1e38f);
        const float sm1 = fmaxf(nm1, -1e38f);
        const float c0  = ex2(fmaxf(m0, -1e38f) - sm0);
        const float c1  = ex2(fmaxf(m1, -1e38f) - sm1);
        m0 = nm0; m1 = nm1;
        l0 *= c0;  l1 *= c1;
        #pragma unroll
        for (int nt = 0; nt < 8; nt++) {
            acc[nt][0] *= c0; acc[nt][1] *= c0;
            acc[nt][2] *= c1; acc[nt][3] *= c1;
        }

        // ---- p = exp2(s - m) ----
        #pragma unroll
        for (int nt = 0; nt < 8; nt++) {
            sc[nt][0] = ex2(sc[nt][0] - sm0);
            sc[nt][1] = ex2(sc[nt][1] - sm0);
            sc[nt][2] = ex2(sc[nt][2] - sm1);
            sc[nt][3] = ex2(sc[nt][3] - sm1);
            l0 += sc[nt][0] + sc[nt][1];
            l1 += sc[nt][2] + sc[nt][3];
        }

        // ---- O += P V : transpose P (C-layout -> A-layout) via shfl ----
        const int s0l = (lane & ~3) | (t >> 1);
        const int s1l = s0l + 2;
        const bool odd = (t & 1);
        #pragma unroll
        for (int ks = 0; ks < 8; ks++) {
            const float x0 = __shfl_sync(0xffffffffu, sc[ks][0], s0l);
            const float x1 = __shfl_sync(0xffffffffu, sc[ks][1], s0l);
            const float z0 = __shfl_sync(0xffffffffu, sc[ks][2], s0l);
            const float z1 = __shfl_sync(0xffffffffu, sc[ks][3], s0l);
            const float y0 = __shfl_sync(0xffffffffu, sc[ks][0], s1l);
            const float y1 = __shfl_sync(0xffffffffu, sc[ks][1], s1l);
            const float u0 = __shfl_sync(0xffffffffu, sc[ks][2], s1l);
            const float u1 = __shfl_sync(0xffffffffu, sc[ks][3], s1l);
            uint32_t ap[4];
            ap[0] = f2tf32(odd ? x1 : x0);
            ap[1] = f2tf32(odd ? z1 : z0);
            ap[2] = f2tf32(odd ? y1 : y0);
            ap[3] = f2tf32(odd ? u1 : u0);
            #pragma unroll
            for (int nd = 0; nd < 8; nd++) {
                uint32_t bf[2];
                bf[0] = __float_as_uint(Vsl[(ks * 8 + t)     * AST + nd * 8 + g]);
                bf[1] = __float_as_uint(Vsl[(ks * 8 + t + 4) * AST + nd * 8 + g]);
                mma_tf32(acc[nd], ap, bf);
            }
        }
    }

    // ---- finalize: quad-reduce l, normalize, store ----
    l0 += __shfl_xor_sync(0xffffffffu, l0, 1);
    l0 += __shfl_xor_sync(0xffffffffu, l0, 2);
    l1 += __shfl_xor_sync(0xffffffffu, l1, 1);
    l1 += __shfl_xor_sync(0xffffffffu, l1, 2);
    const float inv0 = 1.f / l0;
    const float inv1 = 1.f / l1;

    const int row0 = b * T_ + q0 + wq + g;
    #pragma unroll
    for (int nd = 0; nd < 8; nd++) {
        const int col = h * DK_ + nd * 8 + 2 * t;
        float2 o0, o1;
        o0.x = acc[nd][0] * inv0;  o0.y = acc[nd][1] * inv0;
        o1.x = acc[nd][2] * inv1;  o1.y = acc[nd][3] * inv1;
        *(float2*)(Op + (size_t)row0 * E_ + col)       = o0;
        *(float2*)(Op + (size_t)(row0 + 8) * E_ + col) = o1;
    }
}

// ---------------------------------------------------------------------------
extern "C" void kernel_launch(void* const* d_in, const int* in_sizes, int n_in,
                              void* d_out, int out_size)
{
    const float* q  = (const float*)d_in[0];
    const float* k  = (const float*)d_in[1];
    const float* v  = (const float*)d_in[2];
    const float* w  = (const float*)d_in[3];
    const float* Wq = (const float*)d_in[4];
    const float* bq = (const float*)d_in[5];
    const float* Wk = (const float*)d_in[6];
    const float* bk = (const float*)d_in[7];
    const float* Wv = (const float*)d_in[8];
    const float* bv = (const float*)d_in[9];
    const float* Wo = (const float*)d_in[10];
    const float* bo = (const float*)d_in[11];
    float* out = (float*)d_out;

    float *Qp, *Kp, *Vp, *Op;
    cudaGetSymbolAddress((void**)&Qp, g_Q);
    cudaGetSymbolAddress((void**)&Kp, g_K);
    cudaGetSymbolAddress((void**)&Vp, g_V);
    cudaGetSymbolAddress((void**)&Op, g_O);

    cudaFuncSetAttribute(gemm_qkv, cudaFuncAttributeMaxDynamicSharedMemorySize, GEMM_SMEM);
    cudaFuncSetAttribute(gemm_o,   cudaFuncAttributeMaxDynamicSharedMemorySize, GEMM_SMEM);
    cudaFuncSetAttribute(attn_tc,  cudaFuncAttributeMaxDynamicSharedMemorySize, ATTN_SMEM);

    const dim3 qkvGrid(E_ / GBN, M_ / GBM, 3);   // (8, 32, 3)
    gemm_qkv<<<qkvGrid, 256, GEMM_SMEM>>>(q, k, v, Wq, Wk, Wv, bq, bk, bv, Qp, Kp, Vp);

    const dim3 aGrid(T_ / 128, H_, B_);          // (8, 16, 4)
    attn_tc<<<aGrid, 256, ATTN_SMEM>>>(Qp, Kp, Vp, w, Op);

    const dim3 oGrid(E_ / GBN, M_ / GBM);        // (8, 32)
    gemm_o<<<oGrid, 256, GEMM_SMEM>>>(Op, Wo, bo, out);
}

// round 7
// speedup vs baseline: 6.4651x; 1.0268x over previous
#include <cuda_runtime.h>
#include <math.h>
#include <stdint.h>

#define B_   4
#define T_   1024
#define E_   1024
#define H_   16
#define DK_  64
#define M_   (B_ * T_)        // 4096 rows

// Scratch (allocation-free rule: __device__ globals)
__device__ float g_Q[M_ * E_];
__device__ float g_K[M_ * E_];
__device__ float g_V[M_ * E_];
__device__ float g_O[M_ * E_];
// tf32 pre-rounded copies
__device__ float g_q32[M_ * E_];
__device__ float g_k32[M_ * E_];
__device__ float g_v32[M_ * E_];
__device__ float g_W32[4 * E_ * E_];   // Wq, Wk, Wv, Wo

// ---------------------------------------------------------------------------
// helpers
// ---------------------------------------------------------------------------
__device__ __forceinline__ uint32_t smem_u32(const void* p) {
    uint32_t a;
    asm("{ .reg .u64 t; cvta.to.shared.u64 t, %1; cvt.u32.u64 %0, t; }"
        : "=r"(a) : "l"(p));
    return a;
}
__device__ __forceinline__ void cp_async16(uint32_t sdst, const void* gsrc) {
    asm volatile("cp.async.cg.shared.global [%0], [%1], 16;"
                 :: "r"(sdst), "l"(gsrc) : "memory");
}
#define CP_COMMIT() asm volatile("cp.async.commit_group;" ::: "memory")
#define CP_WAIT(n)  asm volatile("cp.async.wait_group %0;" :: "n"(n) : "memory")

__device__ __forceinline__ uint32_t f2tf32(float f) {
    uint32_t r;
    asm("cvt.rna.tf32.f32 %0, %1;" : "=r"(r) : "f"(f));
    return r;
}
__device__ __forceinline__ float ex2(float x) {
    float r; asm("ex2.approx.f32 %0, %1;" : "=f"(r) : "f"(x)); return r;
}
__device__ __forceinline__ void mma_tf32(float* c, const uint32_t* a, const uint32_t* b) {
    asm volatile(
        "mma.sync.aligned.m16n8k8.row.col.f32.tf32.tf32.f32 "
        "{%0,%1,%2,%3}, {%4,%5,%6,%7}, {%8,%9}, {%0,%1,%2,%3};"
        : "+f"(c[0]), "+f"(c[1]), "+f"(c[2]), "+f"(c[3])
        : "r"(a[0]), "r"(a[1]), "r"(a[2]), "r"(a[3]), "r"(b[0]), "r"(b[1]));
}

// ---------------------------------------------------------------------------
// Pre-round kernel: tf32-round q,k,v and the 4 weight matrices (one pass).
// 4M float4 total; grid-stride-free exact cover: 16384 blocks x 256 threads.
// ---------------------------------------------------------------------------
#define SEG_IN  (M_ * E_ / 4)      // 1,048,576 float4 per q/k/v
#define SEG_W   (E_ * E_ / 4)      //   262,144 float4 per weight
__global__ void __launch_bounds__(256)
preround(const float4* __restrict__ q, const float4* __restrict__ k,
         const float4* __restrict__ v,
         const float4* __restrict__ Wq, const float4* __restrict__ Wk,
         const float4* __restrict__ Wv, const float4* __restrict__ Wo,
         float4* __restrict__ rq, float4* __restrict__ rk,
         float4* __restrict__ rv, float4* __restrict__ rW)
{
    int i = blockIdx.x * 256 + threadIdx.x;       // 0 .. 4M-1
    const float4* s;
    float4* d;
    int off;
    if (i < 3 * SEG_IN) {
        const int seg = i / SEG_IN;
        off = i - seg * SEG_IN;
        s = (seg == 0) ? q : (seg == 1) ? k : v;
        d = (seg == 0) ? rq : (seg == 1) ? rk : rv;
    } else {
        i -= 3 * SEG_IN;
        const int seg = i / SEG_W;
        off = i;                                   // rW is contiguous 4*E*E
        s = (seg == 0) ? Wq : (seg == 1) ? Wk : (seg == 2) ? Wv : Wo;
        d = rW;
        s -= (size_t)seg * SEG_W;                  // undo: s indexed by off-seg*SEG_W
        s += (size_t)seg * SEG_W;                  // (keep simple: recompute below)
        // simpler: local index into the selected W
        const int loff = i - seg * SEG_W;
        float4 x = ((seg == 0) ? Wq : (seg == 1) ? Wk : (seg == 2) ? Wv : Wo)[loff];
        x.x = __uint_as_float(f2tf32(x.x));
        x.y = __uint_as_float(f2tf32(x.y));
        x.z = __uint_as_float(f2tf32(x.z));
        x.w = __uint_as_float(f2tf32(x.w));
        rW[i] = x;
        return;
    }
    float4 x = s[off];
    x.x = __uint_as_float(f2tf32(x.x));
    x.y = __uint_as_float(f2tf32(x.y));
    x.z = __uint_as_float(f2tf32(x.z));
    x.w = __uint_as_float(f2tf32(x.w));
    d[off] = x;
}

// ---------------------------------------------------------------------------
// tf32 mma.sync GEMM core:  C[4096,1024] = A[4096,1024] @ W[1024,1024]^T + bias
// 128x128 CTA tile, BK=32, 256 threads (8 warps 4x2), warp tile 32x64.
// Inputs are pre-rounded tf32 -> zero cvt in mainloop.
// ROUND=1: store outputs pre-rounded to tf32.
// ---------------------------------------------------------------------------
#define GBM 128
#define GBN 128
#define GBK 32
#define SSTRIDE 36
#define STAGE_FLOATS (GBM * SSTRIDE)
#define GEMM_SMEM    (2 * 2 * STAGE_FLOATS * 4)      // 73728 bytes

template<int ROUND>
__device__ __forceinline__ void gemm_core(const float* __restrict__ A,
                                          const float* __restrict__ W,
                                          const float* __restrict__ bias,
                                          float* __restrict__ C)
{
    extern __shared__ __align__(16) float smem[];
    float* As = smem;                          // [2][128][36]
    float* Bs = smem + 2 * STAGE_FLOATS;       // [2][128][36]
    const uint32_t sAs = smem_u32(As);
    const uint32_t sBs = smem_u32(Bs);

    const int tid  = threadIdx.x;
    const int wid  = tid >> 5;
    const int lane = tid & 31;
    const int g    = lane >> 2;
    const int t    = lane & 3;
    const int wm   = (wid >> 1) * 32;
    const int wn   = (wid & 1) * 64;
    const int m0   = blockIdx.y * GBM;
    const int n0   = blockIdx.x * GBN;

    float acc[2][8][4] = {};
    const int KTILES = E_ / GBK;

    {
        #pragma unroll
        for (int i = 0; i < 4; i++) {
            const int id = tid + i * 256;
            const int r  = id >> 3;
            const int c4 = (id & 7) * 4;
            cp_async16(sAs + (r * SSTRIDE + c4) * 4, A + (size_t)(m0 + r) * E_ + c4);
            cp_async16(sBs + (r * SSTRIDE + c4) * 4, W + (size_t)(n0 + r) * E_ + c4);
        }
        CP_COMMIT();
    }

    for (int kt = 0; kt < KTILES; kt++) {
        const int s = kt & 1;

        if (kt + 1 < KTILES) {
            const int ns = 1 - s;
            const int kc = (kt + 1) * GBK;
            #pragma unroll
            for (int i = 0; i < 4; i++) {
                const int id = tid + i * 256;
                const int r  = id >> 3;
                const int c4 = (id & 7) * 4;
                cp_async16(sAs + (ns * STAGE_FLOATS + r * SSTRIDE + c4) * 4,
                           A + (size_t)(m0 + r) * E_ + kc + c4);
                cp_async16(sBs + (ns * STAGE_FLOATS + r * SSTRIDE + c4) * 4,
                           W + (size_t)(n0 + r) * E_ + kc + c4);
            }
            CP_COMMIT();
            CP_WAIT(1);
        } else {
            CP_WAIT(0);
        }
        __syncthreads();

        const float* Asl = As + s * STAGE_FLOATS;
        const float* Bsl = Bs + s * STAGE_FLOATS;

        #pragma unroll
        for (int kk = 0; kk < 4; kk++) {
            const int kb = kk * 8;
            uint32_t bf[8][2];
            #pragma unroll
            for (int ni = 0; ni < 8; ni++) {
                const int n = wn + ni * 8 + g;
                bf[ni][0] = __float_as_uint(Bsl[n * SSTRIDE + kb + t]);
                bf[ni][1] = __float_as_uint(Bsl[n * SSTRIDE + kb + t + 4]);
            }
            #pragma unroll
            for (int mi = 0; mi < 2; mi++) {
                const int r = wm + mi * 16;
                uint32_t af[4];
                af[0] = __float_as_uint(Asl[(r + g)     * SSTRIDE + kb + t]);
                af[1] = __float_as_uint(Asl[(r + g + 8) * SSTRIDE + kb + t]);
                af[2] = __float_as_uint(Asl[(r + g)     * SSTRIDE + kb + t + 4]);
                af[3] = __float_as_uint(Asl[(r + g + 8) * SSTRIDE + kb + t + 4]);
                #pragma unroll
                for (int ni = 0; ni < 8; ni++)
                    mma_tf32(acc[mi][ni], af, bf[ni]);
            }
        }
        __syncthreads();
    }

    #pragma unroll
    for (int ni = 0; ni < 8; ni++) {
        const int col = n0 + wn + ni * 8 + 2 * t;
        const float2 bv = *(const float2*)(bias + col);
        #pragma unroll
        for (int mi = 0; mi < 2; mi++) {
            const int r0 = m0 + wm + mi * 16 + g;
            float2 o0, o1;
            o0.x = acc[mi][ni][0] + bv.x;
            o0.y = acc[mi][ni][1] + bv.y;
            o1.x = acc[mi][ni][2] + bv.x;
            o1.y = acc[mi][ni][3] + bv.y;
            if (ROUND) {
                o0.x = __uint_as_float(f2tf32(o0.x));
                o0.y = __uint_as_float(f2tf32(o0.y));
                o1.x = __uint_as_float(f2tf32(o1.x));
                o1.y = __uint_as_float(f2tf32(o1.y));
            }
            *(float2*)(C + (size_t)r0 * E_ + col)       = o0;
            *(float2*)(C + (size_t)(r0 + 8) * E_ + col) = o1;
        }
    }
}

// Merged Q/K/V projections: gridDim.z selects which; outputs tf32-rounded.
__global__ void __launch_bounds__(256)
gemm_qkv(const float* __restrict__ q,  const float* __restrict__ k,  const float* __restrict__ v,
         const float* __restrict__ Wqkv,
         const float* __restrict__ bq, const float* __restrict__ bk, const float* __restrict__ bv,
         float* __restrict__ Cq, float* __restrict__ Ck, float* __restrict__ Cv)
{
    const int z = blockIdx.z;
    if (z == 0)      gemm_core<1>(q, Wqkv,                 bq, Cq);
    else if (z == 1) gemm_core<1>(k, Wqkv + 1 * E_ * E_,   bk, Ck);
    else             gemm_core<1>(v, Wqkv + 2 * E_ * E_,   bv, Cv);
}

__global__ void __launch_bounds__(256)
gemm_o(const float* __restrict__ A, const float* __restrict__ W,
       const float* __restrict__ bias, float* __restrict__ C)
{
    gemm_core<0>(A, W, bias, C);
}

// ---------------------------------------------------------------------------
// Tensor-core flash attention (as R5); O stored tf32-rounded for gemm_o.
// ---------------------------------------------------------------------------
#define AST 68
#define KVSTG (64 * AST)
#define KS_OFF(s) ((s) * 2 * KVSTG)
#define VS_OFF(s) ((s) * 2 * KVSTG + KVSTG)
#define WS_OFF(s) (4 * KVSTG + (s) * 128)
#define QS_OFF    (4 * KVSTG + 256)
#define ATTN_SMEM ((QS_OFF + 128 * AST) * 4)

__global__ void __launch_bounds__(256, 1)
attn_tc(const float* __restrict__ Qp, const float* __restrict__ Kp,
        const float* __restrict__ Vp, const float* __restrict__ w,
        float* __restrict__ Op)
{
    extern __shared__ __align__(16) float sm[];
    const uint32_t sbase = smem_u32(sm);
    const int b   = blockIdx.z;
    const int h   = blockIdx.y;
    const int q0  = blockIdx.x * 128;
    const int tid = threadIdx.x;
    const int wid = tid >> 5;
    const int lane = tid & 31;
    const int g = lane >> 2;
    const int t = lane & 3;
    const int wq = wid * 16;

    {
        const float* Qg = Qp + (size_t)(b * T_ + q0) * E_ + h * DK_;
        #pragma unroll
        for (int i = 0; i < 8; i++) {
            const int id = tid + i * 256;
            const int r  = id >> 4;
            const int c4 = (id & 15) * 4;
            cp_async16(sbase + (QS_OFF + r * AST + c4) * 4, Qg + (size_t)r * E_ + c4);
        }
        CP_COMMIT();
    }
    {
        const float* Kg = Kp + (size_t)(b * T_) * E_ + h * DK_;
        const float* Vg = Vp + (size_t)(b * T_) * E_ + h * DK_;
        #pragma unroll
        for (int i = 0; i < 4; i++) {
            const int id = tid + i * 256;
            const int r  = id >> 4;
            const int c4 = (id & 15) * 4;
            cp_async16(sbase + (KS_OFF(0) + r * AST + c4) * 4, Kg + (size_t)r * E_ + c4);
            cp_async16(sbase + (VS_OFF(0) + r * AST + c4) * 4, Vg + (size_t)r * E_ + c4);
        }
        CP_COMMIT();
    }
    if (tid < 64) {
        const float wv = w[b * T_ + tid];
        sm[WS_OFF(0) + tid * 2 + 0] = wv * wv * 0.125f * 1.44269504f;
        sm[WS_OFF(0) + tid * 2 + 1] = (wv < 1e-5f) ? -INFINITY : 0.0f;
    }

    CP_WAIT(1);
    __syncthreads();

    uint32_t aq[8][4];
    #pragma unroll
    for (int ks = 0; ks < 8; ks++) {
        const int kb = ks * 8;
        aq[ks][0] = __float_as_uint(sm[QS_OFF + (wq + g)     * AST + kb + t]);
        aq[ks][1] = __float_as_uint(sm[QS_OFF + (wq + g + 8) * AST + kb + t]);
        aq[ks][2] = __float_as_uint(sm[QS_OFF + (wq + g)     * AST + kb + t + 4]);
        aq[ks][3] = __float_as_uint(sm[QS_OFF + (wq + g + 8) * AST + kb + t + 4]);
    }

    float acc[8][4] = {};
    float m0 = -INFINITY, m1 = -INFINITY, l0 = 0.f, l1 = 0.f;

    const int NT = T_ / 64;
    for (int kt = 0; kt < NT; kt++) {
        const int s = kt & 1;

        CP_WAIT(0);
        __syncthreads();

        if (kt + 1 < NT) {
            const int ns = 1 - s;
            const float* Kg = Kp + (size_t)(b * T_ + (kt + 1) * 64) * E_ + h * DK_;
            const float* Vg = Vp + (size_t)(b * T_ + (kt + 1) * 64) * E_ + h * DK_;
            #pragma unroll
            for (int i = 0; i < 4; i++) {
                const int id = tid + i * 256;
                const int r  = id >> 4;
                const int c4 = (id & 15) * 4;
                cp_async16(sbase + (KS_OFF(ns) + r * AST + c4) * 4, Kg + (size_t)r * E_ + c4);
                cp_async16(sbase + (VS_OFF(ns) + r * AST + c4) * 4, Vg + (size_t)r * E_ + c4);
            }
            CP_COMMIT();
            if (tid < 64) {
                const float wv = w[b * T_ + (kt + 1) * 64 + tid];
                sm[WS_OFF(ns) + tid * 2 + 0] = wv * wv * 0.125f * 1.44269504f;
                sm[WS_OFF(ns) + tid * 2 + 1] = (wv < 1e-5f) ? -INFINITY : 0.0f;
            }
        }

        const float* Ksl = sm + KS_OFF(s);
        const float* Vsl = sm + VS_OFF(s);
        const float* wsl = sm + WS_OFF(s);

        float sc[8][4] = {};
        #pragma unroll
        for (int ks = 0; ks < 8; ks++) {
            const int kb = ks * 8;
            #pragma unroll
            for (int nt = 0; nt < 8; nt++) {
                uint32_t bf[2];
                bf[0] = __float_as_uint(Ksl[(nt * 8 + g) * AST + kb + t]);
                bf[1] = __float_as_uint(Ksl[(nt * 8 + g) * AST + kb + t + 4]);
                mma_tf32(sc[nt], aq[ks], bf);
            }
        }

        float tmax0 = -INFINITY, tmax1 = -INFINITY;
        #pragma unroll
        for (int nt = 0; nt < 8; nt++) {
            const float4 wm4 = *(const float4*)&wsl[(nt * 8 + 2 * t) * 2];
            sc[nt][0] = sc[nt][0] * wm4.x + wm4.y;
            sc[nt][1] = sc[nt][1] * wm4.z + wm4.w;
            sc[nt][2] = sc[nt][2] * wm4.x + wm4.y;
            sc[nt][3] = sc[nt][3] * wm4.z + wm4.w;
            tmax0 = fmaxf(tmax0, fmaxf(sc[nt][0], sc[nt][1]));
            tmax1 = fmaxf(tmax1, fmaxf(sc[nt][2], sc[nt][3]));
        }
        tmax0 = fmaxf(tmax0, __shfl_xor_sync(0xffffffffu, tmax0, 1));
        tmax0 = fmaxf(tmax0, __shfl_xor_sync(0xffffffffu, tmax0, 2));
        tmax1 = fmaxf(tmax1, __shfl_xor_sync(0xffffffffu, tmax1, 1));
        tmax1 = fmaxf(tmax1, __shfl_xor_sync(0xffffffffu, tmax1, 2));

        const float nm0 = fmaxf(m0, tmax0);
        const float nm1 = fmaxf(m1, tmax1);
        const float sm0 = fmaxf(nm0, -1e38f);
        const float sm1 = fmaxf(nm1, -1e38f);
        const float c0  = ex2(fmaxf(m0, -1e38f) - sm0);
        const float c1  = ex2(fmaxf(m1, -1e38f) - sm1);
        m0 = nm0; m1 = nm1;
        l0 *= c0;  l1 *= c1;
        #pragma unroll
        for (int nt = 0; nt < 8; nt++) {
            acc[nt][0] *= c0; acc[nt][1] *= c0;
            acc[nt][2] *= c1; acc[nt][3] *= c1;
        }

        #pragma unroll
        for (int nt = 0; nt < 8; nt++) {
            sc[nt][0] = ex2(sc[nt][0] - sm0);
            sc[nt][1] = ex2(sc[nt][1] - sm0);
            sc[nt][2] = ex2(sc[nt][2] - sm1);
            sc[nt][3] = ex2(sc[nt][3] - sm1);
            l0 += sc[nt][0] + sc[nt][1];
            l1 += sc[nt][2] + sc[nt][3];
        }

        const int s0l = (lane & ~3) | (t >> 1);
        const int s1l = s0l + 2;
        const bool odd = (t & 1);
        #pragma unroll
        for (int ks = 0; ks < 8; ks++) {
            const float x0 = __shfl_sync(0xffffffffu, sc[ks][0], s0l);
            const float x1 = __shfl_sync(0xffffffffu, sc[ks][1], s0l);
            const float z0 = __shfl_sync(0xffffffffu, sc[ks][2], s0l);
            const float z1 = __shfl_sync(0xffffffffu, sc[ks][3], s0l);
            const float y0 = __shfl_sync(0xffffffffu, sc[ks][0], s1l);
            const float y1 = __shfl_sync(0xffffffffu, sc[ks][1], s1l);
            const float u0 = __shfl_sync(0xffffffffu, sc[ks][2], s1l);
            const float u1 = __shfl_sync(0xffffffffu, sc[ks][3], s1l);
            uint32_t ap[4];
            ap[0] = f2tf32(odd ? x1 : x0);
            ap[1] = f2tf32(odd ? z1 : z0);
            ap[2] = f2tf32(odd ? y1 : y0);
            ap[3] = f2tf32(odd ? u1 : u0);
            #pragma unroll
            for (int nd = 0; nd < 8; nd++) {
                uint32_t bf[2];
                bf[0] = __float_as_uint(Vsl[(ks * 8 + t)     * AST + nd * 8 + g]);
                bf[1] = __float_as_uint(Vsl[(ks * 8 + t + 4) * AST + nd * 8 + g]);
                mma_tf32(acc[nd], ap, bf);
            }
        }
    }

    l0 += __shfl_xor_sync(0xffffffffu, l0, 1);
    l0 += __shfl_xor_sync(0xffffffffu, l0, 2);
    l1 += __shfl_xor_sync(0xffffffffu, l1, 1);
    l1 += __shfl_xor_sync(0xffffffffu, l1, 2);
    const float inv0 = 1.f / l0;
    const float inv1 = 1.f / l1;

    const int row0 = b * T_ + q0 + wq + g;
    #pragma unroll
    for (int nd = 0; nd < 8; nd++) {
        const int col = h * DK_ + nd * 8 + 2 * t;
        float2 o0, o1;
        o0.x = __uint_as_float(f2tf32(acc[nd][0] * inv0));
        o0.y = __uint_as_float(f2tf32(acc[nd][1] * inv0));
        o1.x = __uint_as_float(f2tf32(acc[nd][2] * inv1));
        o1.y = __uint_as_float(f2tf32(acc[nd][3] * inv1));
        *(float2*)(Op + (size_t)row0 * E_ + col)       = o0;
        *(float2*)(Op + (size_t)(row0 + 8) * E_ + col) = o1;
    }
}

// ---------------------------------------------------------------------------
extern "C" void kernel_launch(void* const* d_in, const int* in_sizes, int n_in,
                              void* d_out, int out_size)
{
    const float* q  = (const float*)d_in[0];
    const float* k  = (const float*)d_in[1];
    const float* v  = (const float*)d_in[2];
    const float* w  = (const float*)d_in[3];
    const float* Wq = (const float*)d_in[4];
    const float* bq = (const float*)d_in[5];
    const float* Wk = (const float*)d_in[6];
    const float* bk = (const float*)d_in[7];
    const float* Wv = (const float*)d_in[8];
    const float* bv = (const float*)d_in[9];
    const float* Wo = (const float*)d_in[10];
    const float* bo = (const float*)d_in[11];
    float* out = (float*)d_out;

    float *Qp, *Kp, *Vp, *Op, *rq, *rk, *rv, *rW;
    cudaGetSymbolAddress((void**)&Qp, g_Q);
    cudaGetSymbolAddress((void**)&Kp, g_K);
    cudaGetSymbolAddress((void**)&Vp, g_V);
    cudaGetSymbolAddress((void**)&Op, g_O);
    cudaGetSymbolAddress((void**)&rq, g_q32);
    cudaGetSymbolAddress((void**)&rk, g_k32);
    cudaGetSymbolAddress((void**)&rv, g_v32);
    cudaGetSymbolAddress((void**)&rW, g_W32);

    cudaFuncSetAttribute(gemm_qkv, cudaFuncAttributeMaxDynamicSharedMemorySize, GEMM_SMEM);
    cudaFuncSetAttribute(gemm_o,   cudaFuncAttributeMaxDynamicSharedMemorySize, GEMM_SMEM);
    cudaFuncSetAttribute(attn_tc,  cudaFuncAttributeMaxDynamicSharedMemorySize, ATTN_SMEM);

    // 1) pre-round q,k,v + all weights to tf32 (Wo goes to rW + 3*E*E)
    {
        // segment order in g_W32: Wq, Wk, Wv, Wo
        preround<<<16384, 256>>>((const float4*)q, (const float4*)k, (const float4*)v,
                                 (const float4*)Wq, (const float4*)Wk,
                                 (const float4*)Wv, (const float4*)Wo,
                                 (float4*)rq, (float4*)rk, (float4*)rv, (float4*)rW);
    }

    // 2) QKV projections (pre-rounded inputs; zero cvt in mainloop)
    const dim3 qkvGrid(E_ / GBN, M_ / GBM, 3);   // (8, 32, 3)
    gemm_qkv<<<qkvGrid, 256, GEMM_SMEM>>>(rq, rk, rv, rW, bq, bk, bv, Qp, Kp, Vp);

    // 3) attention
    const dim3 aGrid(T_ / 128, H_, B_);          // (8, 16, 4)
    attn_tc<<<aGrid, 256, ATTN_SMEM>>>(Qp, Kp, Vp, w, Op);

    // 4) output projection (O tf32-rounded by attn; Wo pre-rounded)
    const dim3 oGrid(E_ / GBN, M_ / GBM);        // (8, 32)
    gemm_o<<<oGrid, 256, GEMM_SMEM>>>(Op, rW + 3 * (size_t)E_ * E_, bo, out);
}

// round 8
// speedup vs baseline: 6.5244x; 1.0092x over previous
#include <cuda_runtime.h>
#include <math.h>
#include <stdint.h>

#define B_   4
#define T_   1024
#define E_   1024
#define H_   16
#define DK_  64
#define M_   (B_ * T_)        // 4096 rows

// Scratch (allocation-free rule: __device__ globals)
__device__ float g_Q[M_ * E_];
__device__ float g_K[M_ * E_];
__device__ float g_V[M_ * E_];
__device__ float g_O[M_ * E_];
// tf32 pre-rounded copies
__device__ float g_q32[M_ * E_];
__device__ float g_k32[M_ * E_];
__device__ float g_v32[M_ * E_];
__device__ float g_W32[4 * E_ * E_];   // Wq, Wk, Wv, Wo

// ---------------------------------------------------------------------------
// helpers
// ---------------------------------------------------------------------------
__device__ __forceinline__ uint32_t smem_u32(const void* p) {
    uint32_t a;
    asm("{ .reg .u64 t; cvta.to.shared.u64 t, %1; cvt.u32.u64 %0, t; }"
        : "=r"(a) : "l"(p));
    return a;
}
__device__ __forceinline__ void cp_async16(uint32_t sdst, const void* gsrc) {
    asm volatile("cp.async.cg.shared.global [%0], [%1], 16;"
                 :: "r"(sdst), "l"(gsrc) : "memory");
}
#define CP_COMMIT() asm volatile("cp.async.commit_group;" ::: "memory")
#define CP_WAIT(n)  asm volatile("cp.async.wait_group %0;" :: "n"(n) : "memory")

__device__ __forceinline__ uint32_t f2tf32(float f) {
    uint32_t r;
    asm("cvt.rna.tf32.f32 %0, %1;" : "=r"(r) : "f"(f));
    return r;
}
__device__ __forceinline__ float ex2(float x) {
    float r; asm("ex2.approx.f32 %0, %1;" : "=f"(r) : "f"(x)); return r;
}
__device__ __forceinline__ void mma_tf32(float* c, const uint32_t* a, const uint32_t* b) {
    asm volatile(
        "mma.sync.aligned.m16n8k8.row.col.f32.tf32.tf32.f32 "
        "{%0,%1,%2,%3}, {%4,%5,%6,%7}, {%8,%9}, {%0,%1,%2,%3};"
        : "+f"(c[0]), "+f"(c[1]), "+f"(c[2]), "+f"(c[3])
        : "r"(a[0]), "r"(a[1]), "r"(a[2]), "r"(a[3]), "r"(b[0]), "r"(b[1]));
}

// ---------------------------------------------------------------------------
// Pre-round kernel: tf32-round q,k,v and the 4 weight matrices (one pass).
// ---------------------------------------------------------------------------
#define SEG_IN  (M_ * E_ / 4)      // 1,048,576 float4 per q/k/v
#define SEG_W   (E_ * E_ / 4)      //   262,144 float4 per weight
__global__ void __launch_bounds__(256)
preround(const float4* __restrict__ q, const float4* __restrict__ k,
         const float4* __restrict__ v,
         const float4* __restrict__ Wq, const float4* __restrict__ Wk,
         const float4* __restrict__ Wv, const float4* __restrict__ Wo,
         float4* __restrict__ rq, float4* __restrict__ rk,
         float4* __restrict__ rv, float4* __restrict__ rW)
{
    int i = blockIdx.x * 256 + threadIdx.x;       // 0 .. 4M-1
    if (i < 3 * SEG_IN) {
        const int seg = i / SEG_IN;
        const int off = i - seg * SEG_IN;
        const float4* s = (seg == 0) ? q : (seg == 1) ? k : v;
        float4* d       = (seg == 0) ? rq : (seg == 1) ? rk : rv;
        float4 x = s[off];
        x.x = __uint_as_float(f2tf32(x.x));
        x.y = __uint_as_float(f2tf32(x.y));
        x.z = __uint_as_float(f2tf32(x.z));
        x.w = __uint_as_float(f2tf32(x.w));
        d[off] = x;
    } else {
        i -= 3 * SEG_IN;
        const int seg  = i / SEG_W;
        const int loff = i - seg * SEG_W;
        float4 x = ((seg == 0) ? Wq : (seg == 1) ? Wk : (seg == 2) ? Wv : Wo)[loff];
        x.x = __uint_as_float(f2tf32(x.x));
        x.y = __uint_as_float(f2tf32(x.y));
        x.z = __uint_as_float(f2tf32(x.z));
        x.w = __uint_as_float(f2tf32(x.w));
        rW[i] = x;
    }
}

// ---------------------------------------------------------------------------
// tf32 mma.sync GEMM core:  C[4096,1024] = A[4096,1024] @ W[1024,1024]^T + bias
// 128x128 CTA tile, BK=32, 128 threads (4 warps 2x2), warp tile 64x64.
// Per kk-step/warp: 32 LDS -> 32 MMAs (ratio 1.0), 32-acc ILP.
// ---------------------------------------------------------------------------
#define GBM 128
#define GBN 128
#define GBK 32
#define SSTRIDE 36
#define STAGE_FLOATS (GBM * SSTRIDE)
#define GEMM_SMEM    (2 * 2 * STAGE_FLOATS * 4)      // 73728 bytes

template<int ROUND>
__device__ __forceinline__ void gemm_core(const float* __restrict__ A,
                                          const float* __restrict__ W,
                                          const float* __restrict__ bias,
                                          float* __restrict__ C)
{
    extern __shared__ __align__(16) float smem[];
    float* As = smem;                          // [2][128][36]
    float* Bs = smem + 2 * STAGE_FLOATS;       // [2][128][36]
    const uint32_t sAs = smem_u32(As);
    const uint32_t sBs = smem_u32(Bs);

    const int tid  = threadIdx.x;
    const int wid  = tid >> 5;
    const int lane = tid & 31;
    const int g    = lane >> 2;
    const int t    = lane & 3;
    const int wm   = (wid >> 1) * 64;
    const int wn   = (wid & 1) * 64;
    const int m0   = blockIdx.y * GBM;
    const int n0   = blockIdx.x * GBN;

    float acc[4][8][4] = {};
    const int KTILES = E_ / GBK;

    {
        #pragma unroll
        for (int i = 0; i < 8; i++) {
            const int id = tid + i * 128;
            const int r  = id >> 3;
            const int c4 = (id & 7) * 4;
            cp_async16(sAs + (r * SSTRIDE + c4) * 4, A + (size_t)(m0 + r) * E_ + c4);
            cp_async16(sBs + (r * SSTRIDE + c4) * 4, W + (size_t)(n0 + r) * E_ + c4);
        }
        CP_COMMIT();
    }

    for (int kt = 0; kt < KTILES; kt++) {
        const int s = kt & 1;

        if (kt + 1 < KTILES) {
            const int ns = 1 - s;
            const int kc = (kt + 1) * GBK;
            #pragma unroll
            for (int i = 0; i < 8; i++) {
                const int id = tid + i * 128;
                const int r  = id >> 3;
                const int c4 = (id & 7) * 4;
                cp_async16(sAs + (ns * STAGE_FLOATS + r * SSTRIDE + c4) * 4,
                           A + (size_t)(m0 + r) * E_ + kc + c4);
                cp_async16(sBs + (ns * STAGE_FLOATS + r * SSTRIDE + c4) * 4,
                           W + (size_t)(n0 + r) * E_ + kc + c4);
            }
            CP_COMMIT();
            CP_WAIT(1);
        } else {
            CP_WAIT(0);
        }
        __syncthreads();

        const float* Asl = As + s * STAGE_FLOATS;
        const float* Bsl = Bs + s * STAGE_FLOATS;

        #pragma unroll
        for (int kk = 0; kk < 4; kk++) {
            const int kb = kk * 8;
            uint32_t bf[8][2];
            #pragma unroll
            for (int ni = 0; ni < 8; ni++) {
                const int n = wn + ni * 8 + g;
                bf[ni][0] = __float_as_uint(Bsl[n * SSTRIDE + kb + t]);
                bf[ni][1] = __float_as_uint(Bsl[n * SSTRIDE + kb + t + 4]);
            }
            #pragma unroll
            for (int mi = 0; mi < 4; mi++) {
                const int r = wm + mi * 16;
                uint32_t af[4];
                af[0] = __float_as_uint(Asl[(r + g)     * SSTRIDE + kb + t]);
                af[1] = __float_as_uint(Asl[(r + g + 8) * SSTRIDE + kb + t]);
                af[2] = __float_as_uint(Asl[(r + g)     * SSTRIDE + kb + t + 4]);
                af[3] = __float_as_uint(Asl[(r + g + 8) * SSTRIDE + kb + t + 4]);
                #pragma unroll
                for (int ni = 0; ni < 8; ni++)
                    mma_tf32(acc[mi][ni], af, bf[ni]);
            }
        }
        __syncthreads();
    }

    #pragma unroll
    for (int ni = 0; ni < 8; ni++) {
        const int col = n0 + wn + ni * 8 + 2 * t;
        const float2 bv = *(const float2*)(bias + col);
        #pragma unroll
        for (int mi = 0; mi < 4; mi++) {
            const int r0 = m0 + wm + mi * 16 + g;
            float2 o0, o1;
            o0.x = acc[mi][ni][0] + bv.x;
            o0.y = acc[mi][ni][1] + bv.y;
            o1.x = acc[mi][ni][2] + bv.x;
            o1.y = acc[mi][ni][3] + bv.y;
            if (ROUND) {
                o0.x = __uint_as_float(f2tf32(o0.x));
                o0.y = __uint_as_float(f2tf32(o0.y));
                o1.x = __uint_as_float(f2tf32(o1.x));
                o1.y = __uint_as_float(f2tf32(o1.y));
            }
            *(float2*)(C + (size_t)r0 * E_ + col)       = o0;
            *(float2*)(C + (size_t)(r0 + 8) * E_ + col) = o1;
        }
    }
}

// Merged Q/K/V projections: gridDim.z selects which; outputs tf32-rounded.
__global__ void __launch_bounds__(128)
gemm_qkv(const float* __restrict__ q,  const float* __restrict__ k,  const float* __restrict__ v,
         const float* __restrict__ Wqkv,
         const float* __restrict__ bq, const float* __restrict__ bk, const float* __restrict__ bv,
         float* __restrict__ Cq, float* __restrict__ Ck, float* __restrict__ Cv)
{
    const int z = blockIdx.z;
    if (z == 0)      gemm_core<1>(q, Wqkv,                 bq, Cq);
    else if (z == 1) gemm_core<1>(k, Wqkv + 1 * E_ * E_,   bk, Ck);
    else             gemm_core<1>(v, Wqkv + 2 * E_ * E_,   bv, Cv);
}

__global__ void __launch_bounds__(128)
gemm_o(const float* __restrict__ A, const float* __restrict__ W,
       const float* __restrict__ bias, float* __restrict__ C)
{
    gemm_core<0>(A, W, bias, C);
}

// ---------------------------------------------------------------------------
// Tensor-core flash attention (as R5); O stored tf32-rounded for gemm_o.
// ---------------------------------------------------------------------------
#define AST 68
#define KVSTG (64 * AST)
#define KS_OFF(s) ((s) * 2 * KVSTG)
#define VS_OFF(s) ((s) * 2 * KVSTG + KVSTG)
#define WS_OFF(s) (4 * KVSTG + (s) * 128)
#define QS_OFF    (4 * KVSTG + 256)
#define ATTN_SMEM ((QS_OFF + 128 * AST) * 4)

__global__ void __launch_bounds__(256, 1)
attn_tc(const float* __restrict__ Qp, const float* __restrict__ Kp,
        const float* __restrict__ Vp, const float* __restrict__ w,
        float* __restrict__ Op)
{
    extern __shared__ __align__(16) float sm[];
    const uint32_t sbase = smem_u32(sm);
    const int b   = blockIdx.z;
    const int h   = blockIdx.y;
    const int q0  = blockIdx.x * 128;
    const int tid = threadIdx.x;
    const int wid = tid >> 5;
    const int lane = tid & 31;
    const int g = lane >> 2;
    const int t = lane & 3;
    const int wq = wid * 16;

    {
        const float* Qg = Qp + (size_t)(b * T_ + q0) * E_ + h * DK_;
        #pragma unroll
        for (int i = 0; i < 8; i++) {
            const int id = tid + i * 256;
            const int r  = id >> 4;
            const int c4 = (id & 15) * 4;
            cp_async16(sbase + (QS_OFF + r * AST + c4) * 4, Qg + (size_t)r * E_ + c4);
        }
        CP_COMMIT();
    }
    {
        const float* Kg = Kp + (size_t)(b * T_) * E_ + h * DK_;
        const float* Vg = Vp + (size_t)(b * T_) * E_ + h * DK_;
        #pragma unroll
        for (int i = 0; i < 4; i++) {
            const int id = tid + i * 256;
            const int r  = id >> 4;
            const int c4 = (id & 15) * 4;
            cp_async16(sbase + (KS_OFF(0) + r * AST + c4) * 4, Kg + (size_t)r * E_ + c4);
            cp_async16(sbase + (VS_OFF(0) + r * AST + c4) * 4, Vg + (size_t)r * E_ + c4);
        }
        CP_COMMIT();
    }
    if (tid < 64) {
        const float wv = w[b * T_ + tid];
        sm[WS_OFF(0) + tid * 2 + 0] = wv * wv * 0.125f * 1.44269504f;
        sm[WS_OFF(0) + tid * 2 + 1] = (wv < 1e-5f) ? -INFINITY : 0.0f;
    }

    CP_WAIT(1);
    __syncthreads();

    uint32_t aq[8][4];
    #pragma unroll
    for (int ks = 0; ks < 8; ks++) {
        const int kb = ks * 8;
        aq[ks][0] = __float_as_uint(sm[QS_OFF + (wq + g)     * AST + kb + t]);
        aq[ks][1] = __float_as_uint(sm[QS_OFF + (wq + g + 8) * AST + kb + t]);
        aq[ks][2] = __float_as_uint(sm[QS_OFF + (wq + g)     * AST + kb + t + 4]);
        aq[ks][3] = __float_as_uint(sm[QS_OFF + (wq + g + 8) * AST + kb + t + 4]);
    }

    float acc[8][4] = {};
    float m0 = -INFINITY, m1 = -INFINITY, l0 = 0.f, l1 = 0.f;

    const int NT = T_ / 64;
    for (int kt = 0; kt < NT; kt++) {
        const int s = kt & 1;

        CP_WAIT(0);
        __syncthreads();

        if (kt + 1 < NT) {
            const int ns = 1 - s;
            const float* Kg = Kp + (size_t)(b * T_ + (kt + 1) * 64) * E_ + h * DK_;
            const float* Vg = Vp + (size_t)(b * T_ + (kt + 1) * 64) * E_ + h * DK_;
            #pragma unroll
            for (int i = 0; i < 4; i++) {
                const int id = tid + i * 256;
                const int r  = id >> 4;
                const int c4 = (id & 15) * 4;
                cp_async16(sbase + (KS_OFF(ns) + r * AST + c4) * 4, Kg + (size_t)r * E_ + c4);
                cp_async16(sbase + (VS_OFF(ns) + r * AST + c4) * 4, Vg + (size_t)r * E_ + c4);
            }
            CP_COMMIT();
            if (tid < 64) {
                const float wv = w[b * T_ + (kt + 1) * 64 + tid];
                sm[WS_OFF(ns) + tid * 2 + 0] = wv * wv * 0.125f * 1.44269504f;
                sm[WS_OFF(ns) + tid * 2 + 1] = (wv < 1e-5f) ? -INFINITY : 0.0f;
            }
        }

        const float* Ksl = sm + KS_OFF(s);
        const float* Vsl = sm + VS_OFF(s);
        const float* wsl = sm + WS_OFF(s);

        float sc[8][4] = {};
        #pragma unroll
        for (int ks = 0; ks < 8; ks++) {
            const int kb = ks * 8;
            #pragma unroll
            for (int nt = 0; nt < 8; nt++) {
                uint32_t bf[2];
                bf[0] = __float_as_uint(Ksl[(nt * 8 + g) * AST + kb + t]);
                bf[1] = __float_as_uint(Ksl[(nt * 8 + g) * AST + kb + t + 4]);
                mma_tf32(sc[nt], aq[ks], bf);
            }
        }

        float tmax0 = -INFINITY, tmax1 = -INFINITY;
        #pragma unroll
        for (int nt = 0; nt < 8; nt++) {
            const float4 wm4 = *(const float4*)&wsl[(nt * 8 + 2 * t) * 2];
            sc[nt][0] = sc[nt][0] * wm4.x + wm4.y;
            sc[nt][1] = sc[nt][1] * wm4.z + wm4.w;
            sc[nt][2] = sc[nt][2] * wm4.x + wm4.y;
            sc[nt][3] = sc[nt][3] * wm4.z + wm4.w;
            tmax0 = fmaxf(tmax0, fmaxf(sc[nt][0], sc[nt][1]));
            tmax1 = fmaxf(tmax1, fmaxf(sc[nt][2], sc[nt][3]));
        }
        tmax0 = fmaxf(tmax0, __shfl_xor_sync(0xffffffffu, tmax0, 1));
        tmax0 = fmaxf(tmax0, __shfl_xor_sync(0xffffffffu, tmax0, 2));
        tmax1 = fmaxf(tmax1, __shfl_xor_sync(0xffffffffu, tmax1, 1));
        tmax1 = fmaxf(tmax1, __shfl_xor_sync(0xffffffffu, tmax1, 2));

        const float nm0 = fmaxf(m0, tmax0);
        const float nm1 = fmaxf(m1, tmax1);
        const float sm0 = fmaxf(nm0, -1e38f);
        const float sm1 = fmaxf(nm1, -1e38f);
        const float c0  = ex2(fmaxf(m0, -1e38f) - sm0);
        const float c1  = ex2(fmaxf(m1, -1e38f) - sm1);
        m0 = nm0; m1 = nm1;
        l0 *= c0;  l1 *= c1;
        #pragma unroll
        for (int nt = 0; nt < 8; nt++) {
            acc[nt][0] *= c0; acc[nt][1] *= c0;
            acc[nt][2] *= c1; acc[nt][3] *= c1;
        }

        #pragma unroll
        for (int nt = 0; nt < 8; nt++) {
            sc[nt][0] = ex2(sc[nt][0] - sm0);
            sc[nt][1] = ex2(sc[nt][1] - sm0);
            sc[nt][2] = ex2(sc[nt][2] - sm1);
            sc[nt][3] = ex2(sc[nt][3] - sm1);
            l0 += sc[nt][0] + sc[nt][1];
            l1 += sc[nt][2] + sc[nt][3];
        }

        const int s0l = (lane & ~3) | (t >> 1);
        const int s1l = s0l + 2;
        const bool odd = (t & 1);
        #pragma unroll
        for (int ks = 0; ks < 8; ks++) {
            const float x0 = __shfl_sync(0xffffffffu, sc[ks][0], s0l);
            const float x1 = __shfl_sync(0xffffffffu, sc[ks][1], s0l);
            const float z0 = __shfl_sync(0xffffffffu, sc[ks][2], s0l);
            const float z1 = __shfl_sync(0xffffffffu, sc[ks][3], s0l);
            const float y0 = __shfl_sync(0xffffffffu, sc[ks][0], s1l);
            const float y1 = __shfl_sync(0xffffffffu, sc[ks][1], s1l);
            const float u0 = __shfl_sync(0xffffffffu, sc[ks][2], s1l);
            const float u1 = __shfl_sync(0xffffffffu, sc[ks][3], s1l);
            uint32_t ap[4];
            ap[0] = f2tf32(odd ? x1 : x0);
            ap[1] = f2tf32(odd ? z1 : z0);
            ap[2] = f2tf32(odd ? y1 : y0);
            ap[3] = f2tf32(odd ? u1 : u0);
            #pragma unroll
            for (int nd = 0; nd < 8; nd++) {
                uint32_t bf[2];
                bf[0] = __float_as_uint(Vsl[(ks * 8 + t)     * AST + nd * 8 + g]);
                bf[1] = __float_as_uint(Vsl[(ks * 8 + t + 4) * AST + nd * 8 + g]);
                mma_tf32(acc[nd], ap, bf);
            }
        }
    }

    l0 += __shfl_xor_sync(0xffffffffu, l0, 1);
    l0 += __shfl_xor_sync(0xffffffffu, l0, 2);
    l1 += __shfl_xor_sync(0xffffffffu, l1, 1);
    l1 += __shfl_xor_sync(0xffffffffu, l1, 2);
    const float inv0 = 1.f / l0;
    const float inv1 = 1.f / l1;

    const int row0 = b * T_ + q0 + wq + g;
    #pragma unroll
    for (int nd = 0; nd < 8; nd++) {
        const int col = h * DK_ + nd * 8 + 2 * t;
        float2 o0, o1;
        o0.x = __uint_as_float(f2tf32(acc[nd][0] * inv0));
        o0.y = __uint_as_float(f2tf32(acc[nd][1] * inv0));
        o1.x = __uint_as_float(f2tf32(acc[nd][2] * inv1));
        o1.y = __uint_as_float(f2tf32(acc[nd][3] * inv1));
        *(float2*)(Op + (size_t)row0 * E_ + col)       = o0;
        *(float2*)(Op + (size_t)(row0 + 8) * E_ + col) = o1;
    }
}

// ---------------------------------------------------------------------------
extern "C" void kernel_launch(void* const* d_in, const int* in_sizes, int n_in,
                              void* d_out, int out_size)
{
    const float* q  = (const float*)d_in[0];
    const float* k  = (const float*)d_in[1];
    const float* v  = (const float*)d_in[2];
    const float* w  = (const float*)d_in[3];
    const float* Wq = (const float*)d_in[4];
    const float* bq = (const float*)d_in[5];
    const float* Wk = (const float*)d_in[6];
    const float* bk = (const float*)d_in[7];
    const float* Wv = (const float*)d_in[8];
    const float* bv = (const float*)d_in[9];
    const float* Wo = (const float*)d_in[10];
    const float* bo = (const float*)d_in[11];
    float* out = (float*)d_out;

    float *Qp, *Kp, *Vp, *Op, *rq, *rk, *rv, *rW;
    cudaGetSymbolAddress((void**)&Qp, g_Q);
    cudaGetSymbolAddress((void**)&Kp, g_K);
    cudaGetSymbolAddress((void**)&Vp, g_V);
    cudaGetSymbolAddress((void**)&Op, g_O);
    cudaGetSymbolAddress((void**)&rq, g_q32);
    cudaGetSymbolAddress((void**)&rk, g_k32);
    cudaGetSymbolAddress((void**)&rv, g_v32);
    cudaGetSymbolAddress((void**)&rW, g_W32);

    cudaFuncSetAttribute(gemm_qkv, cudaFuncAttributeMaxDynamicSharedMemorySize, GEMM_SMEM);
    cudaFuncSetAttribute(gemm_o,   cudaFuncAttributeMaxDynamicSharedMemorySize, GEMM_SMEM);
    cudaFuncSetAttribute(attn_tc,  cudaFuncAttributeMaxDynamicSharedMemorySize, ATTN_SMEM);

    // 1) pre-round q,k,v + all weights to tf32 (order in g_W32: Wq, Wk, Wv, Wo)
    preround<<<16384, 256>>>((const float4*)q, (const float4*)k, (const float4*)v,
                             (const float4*)Wq, (const float4*)Wk,
                             (const float4*)Wv, (const float4*)Wo,
                             (float4*)rq, (float4*)rk, (float4*)rv, (float4*)rW);

    // 2) QKV projections
    const dim3 qkvGrid(E_ / GBN, M_ / GBM, 3);   // (8, 32, 3)
    gemm_qkv<<<qkvGrid, 128, GEMM_SMEM>>>(rq, rk, rv, rW, bq, bk, bv, Qp, Kp, Vp);

    // 3) attention
    const dim3 aGrid(T_ / 128, H_, B_);          // (8, 16, 4)
    attn_tc<<<aGrid, 256, ATTN_SMEM>>>(Qp, Kp, Vp, w, Op);

    // 4) output projection
    const dim3 oGrid(E_ / GBN, M_ / GBM);        // (8, 32)
    gemm_o<<<oGrid, 128, GEMM_SMEM>>>(Op, rW + 3 * (size_t)E_ * E_, bo, out);
}